// round 15
// baseline (speedup 1.0000x reference)
#include <cuda_runtime.h>
#include <cuda_bf16.h>
#include <math.h>
#include <stdint.h>

#define Bn 4096
#define Ln 32
#define Cn 28
#define Hn 512
#define Tn 32
#define NG 2048          // 4*H
#define KA 1664          // 512 h_hi | 512 h_lo | 512 h_hi | 32 ctx_hi | 32 ctx_lo | 32 ctx_hi | 32 pad
#define NCHUNK 26        // KA / 64
#define ROWB 144         // 64 bf16 (128B) + 16B pad per smem row
#define BUFB (128 * ROWB)        // 18432 B per tile buffer
// dynamic smem: A0 A1 A2 B0 B1 B2  (3-stage pipeline)
#define AOFF 0
#define BOFF (3 * BUFB)
#define SMEM_DYN (6 * BUFB)      // 110592

// ---------------- device scratch ----------------
__device__ float x_g[Bn * Ln * Cn];
__device__ float ua_g[Bn * Ln];
__device__ float br_g[NG];
__device__ float c_g[Bn * Hn];
__device__ float wa_g[2][Bn];                              // ping-pong fc1 dot
__device__ __align__(16) __nv_bfloat16 A_bf[2][Bn * KA];   // ping-pong h/ctx splits
__device__ __align__(16) __nv_bfloat16 B_bf[NG * KA];

// ---------------- asm helpers ----------------
__device__ __forceinline__ uint32_t smem_u32(const void* p) {
    uint32_t a;
    asm("{ .reg .u64 t; cvta.to.shared.u64 t, %1; cvt.u32.u64 %0, t; }" : "=r"(a) : "l"(p));
    return a;
}
__device__ __forceinline__ void ldsm_x4(uint32_t a, uint32_t& r0, uint32_t& r1, uint32_t& r2, uint32_t& r3) {
    asm volatile("ldmatrix.sync.aligned.m8n8.x4.shared.b16 {%0,%1,%2,%3}, [%4];"
                 : "=r"(r0), "=r"(r1), "=r"(r2), "=r"(r3) : "r"(a));
}
__device__ __forceinline__ void mma_bf16(float* c, uint32_t a0, uint32_t a1, uint32_t a2, uint32_t a3,
                                         uint32_t b0, uint32_t b1) {
    asm volatile("mma.sync.aligned.m16n8k16.row.col.f32.bf16.bf16.f32 "
                 "{%0,%1,%2,%3},{%4,%5,%6,%7},{%8,%9},{%0,%1,%2,%3};"
                 : "+f"(c[0]), "+f"(c[1]), "+f"(c[2]), "+f"(c[3])
                 : "r"(a0), "r"(a1), "r"(a2), "r"(a3), "r"(b0), "r"(b1));
}
__device__ __forceinline__ void cpa16(uint32_t s, const void* g) {
    asm volatile("cp.async.cg.shared.global [%0], [%1], 16;" :: "r"(s), "l"(g));
}
__device__ __forceinline__ void cpa_commit() { asm volatile("cp.async.commit_group;" ::: "memory"); }
template <int N> __device__ __forceinline__ void cpa_wait() {
    asm volatile("cp.async.wait_group %0;" :: "n"(N) : "memory");
}

// ---------------- front-end conv ----------------
__global__ void conv_front(const float* __restrict__ in, const float* __restrict__ mask,
                           const float* __restrict__ w1, const float* __restrict__ b1,
                           const float* __restrict__ cw, const float* __restrict__ cb)
{
    __shared__ float ws[Cn * Cn * 3];
    __shared__ float cws[Cn];
    int tid = threadIdx.x;
    for (int i = tid; i < Cn * Cn * 3; i += blockDim.x) ws[i] = w1[i];
    if (tid < Cn) cws[tid] = cw[tid];
    __syncthreads();

    int idx = blockIdx.x * blockDim.x + tid;
    if (idx >= Bn * Ln) return;
    int b = idx / Ln, l = idx % Ln;

    float xin[3][Cn];
    #pragma unroll
    for (int k = 0; k < 3; k++) {
        int ll = l + k - 1;
        if (ll >= 0 && ll < Ln) {
            #pragma unroll
            for (int c = 0; c < Cn; c++) xin[k][c] = in[(b * Ln + ll) * Cn + c];
        } else {
            #pragma unroll
            for (int c = 0; c < Cn; c++) xin[k][c] = 0.f;
        }
    }
    float m = mask[idx];
    float ua = 0.f;
    for (int co = 0; co < Cn; co++) {
        float acc = b1[co];
        #pragma unroll
        for (int ci = 0; ci < Cn; ci++) {
            const float* wp = &ws[(co * Cn + ci) * 3];
            acc += xin[0][ci] * wp[0] + xin[1][ci] * wp[1] + xin[2][ci] * wp[2];
        }
        float ym = acc * m;
        float e  = ym > 0.f ? ym : (expf(ym) - 1.f);
        float xv = e + xin[1][co];
        x_g[idx * Cn + co] = xv;
        ua += xv * cws[co];
    }
    ua_g[idx] = (ua + cb[0]) * m;
}

// ---------------- build bf16-split B + bias (gate-interleaved n) ----------------
// n = 16*(j>>2) + 2*(j&3) + (g&1) + 8*(g>>1), g in {0:i,1:f,2:g,3:o}
__global__ void build_B(const float* __restrict__ whh, const float* __restrict__ wih,
                        const float* __restrict__ bih, const float* __restrict__ bhh)
{
    int idx = blockIdx.x * blockDim.x + threadIdx.x;
    if (idx < NG * KA) {
        int n = idx / KA, kl = idx % KA;
        int within = n & 15;
        int j = (n >> 4) * 4 + ((within & 7) >> 1);
        int g = (within & 1) + ((within >> 3) << 1);     // 0:i 1:f 2:g 3:o
        float v = 0.f; bool lo = false;
        if (kl < 512)        { v = whh[(g * Hn + j) * Hn + kl]; }
        else if (kl < 1024)  { v = whh[(g * Hn + j) * Hn + (kl - 512)]; }
        else if (kl < 1536)  { v = whh[(g * Hn + j) * Hn + (kl - 1024)]; lo = true; }
        else if (kl < 1632) {
            int c = (kl - 1536) & 31;
            int sec = (kl - 1536) >> 5;                  // 0: Wir_hi, 1: Wir_hi, 2: Wir_lo
            if (c < Cn) { v = wih[(g * Hn + j) * Cn + c]; lo = (sec == 2); }
        }                                                 // kl >= 1632: pad, v=0
        __nv_bfloat16 hi = __float2bfloat16(v);
        B_bf[idx] = lo ? __float2bfloat16(v - __bfloat162float(hi)) : hi;
    }
    if (idx < NG) {
        int within = idx & 15;
        int j = (idx >> 4) * 4 + ((within & 7) >> 1);
        int g = (within & 1) + ((within >> 3) << 1);
        br_g[idx] = bih[g * Hn + j] + bhh[g * Hn + j];
    }
}

// ---------------- init ----------------
__global__ void init_state(float* __restrict__ out, const float* __restrict__ mask,
                           const float* __restrict__ c2b)
{
    int idx = blockIdx.x * blockDim.x + threadIdx.x;
    if (idx < Bn * KA) ((uint32_t*)A_bf)[idx] = 0u;       // both ping-pong buffers
    if (idx < Bn * Hn) c_g[idx] = 0.f;
    if (idx < Bn) { wa_g[0][idx] = 0.f; wa_g[1][idx] = 0.f; }
    if (idx < Bn * Tn) out[idx] = c2b[0] * mask[idx];
}

// ---------------- per-step attention + context (writes ctx splits into A[t&1]) ----------------
__global__ void attn_ctx(int t, const float* __restrict__ fc1b, const float* __restrict__ bias)
{
    int gw = (blockIdx.x * blockDim.x + threadIdx.x) >> 5;
    int lane = threadIdx.x & 31;
    if (gw >= Bn) return;

    float wa = wa_g[t & 1][gw] + fc1b[0];
    if (lane == 0) wa_g[(t + 1) & 1][gw] = 0.f;   // zero accumulator for this step's epilogue

    float v = ua_g[gw * Ln + lane] + wa;
    float lr = v > 0.f ? v : 0.01f * v;
    float logit = lr + bias[gw * Ln + lane];
    float mx = logit;
    #pragma unroll
    for (int o = 16; o > 0; o >>= 1) mx = fmaxf(mx, __shfl_xor_sync(0xffffffffu, mx, o));
    float e = expf(logit - mx);
    float se = e;
    #pragma unroll
    for (int o = 16; o > 0; o >>= 1) se += __shfl_xor_sync(0xffffffffu, se, o);
    float attn = e / se;

    float ctx = 0.f;
    const float* xb = x_g + (size_t)gw * Ln * Cn;
    #pragma unroll
    for (int l = 0; l < Ln; l++) {
        float al = __shfl_sync(0xffffffffu, attn, l);
        if (lane < Cn) ctx = fmaf(al, xb[l * Cn + lane], ctx);
    }
    if (lane < Cn) {
        __nv_bfloat16 hi = __float2bfloat16(ctx);
        __nv_bfloat16 lo = __float2bfloat16(ctx - __bfloat162float(hi));
        __nv_bfloat16* ab = A_bf[t & 1] + (size_t)gw * KA + 1536;
        ab[lane] = hi; ab[32 + lane] = lo; ab[64 + lane] = hi;
    }
}

// ---------------- per-step HMMA GEMM (128x128 tile, K-chunk 64, 3-stage) + LSTM epilogue ----------------
__global__ void __launch_bounds__(256, 2) step_mma(int t, const float* __restrict__ c2w,
                                                   const float* __restrict__ fc1w,
                                                   const float* __restrict__ mask,
                                                   float* __restrict__ out)
{
    extern __shared__ __align__(16) char dsm[];
    __shared__ float outred[128];
    __shared__ float wared[128];

    int tid = threadIdx.x;
    int lane = tid & 31, wid = tid >> 5;
    int wm = wid & 3, wn = wid >> 2;
    int m0 = blockIdx.x * 128;
    int n0 = blockIdx.y * 128;

    uint32_t sbase = smem_u32(dsm);

    const __nv_bfloat16* Ag = A_bf[t & 1] + (size_t)m0 * KA;        // read h_t / ctx_t
    __nv_bfloat16* Anext = A_bf[(t + 1) & 1];                       // write h_{t+1}
    const __nv_bfloat16* Bg = B_bf + (size_t)n0 * KA;

    // loader: 32 rows/pass x 8x16B parts; 4 passes per tensor per chunk
    int lm = tid >> 3;            // 0..31
    int lp = tid & 7;             // 16B part (128B per row)

    #define LOADAB(cc, buf) do {                                                         \
        int _k0 = (cc) * 64;                                                             \
        _Pragma("unroll")                                                                \
        for (int s = 0; s < 4; s++) {                                                    \
            int m = s * 32 + lm;                                                         \
            cpa16(sbase + AOFF + (buf) * BUFB + m * ROWB + lp * 16,                      \
                  Ag + (size_t)m * KA + _k0 + lp * 8);                                   \
            cpa16(sbase + BOFF + (buf) * BUFB + m * ROWB + lp * 16,                      \
                  Bg + (size_t)m * KA + _k0 + lp * 8);                                   \
        }                                                                                \
    } while (0)

    LOADAB(0, 0); cpa_commit();
    LOADAB(1, 1); cpa_commit();

    float acc[2][8][4];
    #pragma unroll
    for (int i = 0; i < 2; i++)
        #pragma unroll
        for (int j = 0; j < 8; j++)
            #pragma unroll
            for (int k = 0; k < 4; k++) acc[i][j][k] = 0.f;

    int a_row_lo = (lane & 7) + ((lane >> 3) & 1) * 8;
    int a_kb     = (lane >> 4) * 16;
    int b_row_lo = (lane & 7) + ((lane >> 4) & 1) * 8;
    int b_kb     = ((lane >> 3) & 1) * 16;

    // 3-stage pipeline, ONE barrier per chunk:
    // top of chunk c: wait for chunk c's load; sync (also proves all warps done
    // computing chunk c-1, so buf (c-1)%3 == (c+2)%3 is free); issue load c+2; compute c.
    for (int c = 0; c < NCHUNK; c++) {
        if (c < NCHUNK - 1) cpa_wait<1>();
        else                cpa_wait<0>();
        __syncthreads();
        if (c + 2 < NCHUNK) { LOADAB(c + 2, (c + 2) % 3); cpa_commit(); }

        uint32_t ab = sbase + AOFF + (c % 3) * BUFB;
        uint32_t bb = sbase + BOFF + (c % 3) * BUFB;
        #pragma unroll
        for (int kk = 0; kk < 4; kk++) {
            int kb = kk * 32;    // 16 bf16 = 32B per k-step
            uint32_t af[2][4];
            #pragma unroll
            for (int mt = 0; mt < 2; mt++)
                ldsm_x4(ab + (wm * 32 + mt * 16 + a_row_lo) * ROWB + kb + a_kb,
                        af[mt][0], af[mt][1], af[mt][2], af[mt][3]);
            #pragma unroll
            for (int p = 0; p < 4; p++) {
                uint32_t b0, b1, b2, b3;
                ldsm_x4(bb + (wn * 64 + p * 16 + b_row_lo) * ROWB + kb + b_kb, b0, b1, b2, b3);
                #pragma unroll
                for (int mt = 0; mt < 2; mt++) {
                    mma_bf16(acc[mt][p * 2 + 0], af[mt][0], af[mt][1], af[mt][2], af[mt][3], b0, b1);
                    mma_bf16(acc[mt][p * 2 + 1], af[mt][0], af[mt][1], af[mt][2], af[mt][3], b2, b3);
                }
            }
        }
    }
    __syncthreads();   // all warps done with last buffer before epilogue reuses smem

    // ---- epilogue: LSTM cell + out dot + fc1 dot + bf16-split h into A[(t+1)&1] ----
    if (tid < 128) { outred[tid] = 0.f; wared[tid] = 0.f; }
    __syncthreads();

    float pr[4] = {0.f, 0.f, 0.f, 0.f};
    float pw[4] = {0.f, 0.f, 0.f, 0.f};
    int u = lane & 3;

    #pragma unroll
    for (int p = 0; p < 4; p++) {
        int nb16 = n0 + wn * 64 + p * 16;
        int j = (nb16 >> 4) * 4 + u;
        float bi  = br_g[nb16 + u * 2 + 0];
        float bfv = br_g[nb16 + u * 2 + 1];
        float bg  = br_g[nb16 + 8 + u * 2 + 0];
        float bo  = br_g[nb16 + 8 + u * 2 + 1];
        float wc2 = c2w[j], wf1 = fc1w[j];
        #pragma unroll
        for (int mt = 0; mt < 2; mt++) {
            #pragma unroll
            for (int rh = 0; rh < 2; rh++) {
                int row = wm * 32 + mt * 16 + (lane >> 2) + rh * 8;
                int b = m0 + row;
                float ig = acc[mt][p * 2 + 0][rh * 2 + 0] + bi;
                float fg = acc[mt][p * 2 + 0][rh * 2 + 1] + bfv;
                float gg = acc[mt][p * 2 + 1][rh * 2 + 0] + bg;
                float og = acc[mt][p * 2 + 1][rh * 2 + 1] + bo;
                float si = 1.f / (1.f + expf(-ig));
                float sf = 1.f / (1.f + expf(-fg));
                float so = 1.f / (1.f + expf(-og));
                float cnew = sf * c_g[b * Hn + j] + si * tanhf(gg);
                float hn = so * tanhf(cnew);
                c_g[b * Hn + j] = cnew;
                __nv_bfloat16 hi = __float2bfloat16(hn);
                __nv_bfloat16 lo = __float2bfloat16(hn - __bfloat162float(hi));
                __nv_bfloat16* arow = Anext + (size_t)b * KA;
                arow[j] = hi; arow[512 + j] = lo; arow[1024 + j] = hi;
                pr[mt * 2 + rh] = fmaf(hn, wc2, pr[mt * 2 + rh]);
                pw[mt * 2 + rh] = fmaf(hn, wf1, pw[mt * 2 + rh]);
            }
        }
    }
    #pragma unroll
    for (int i = 0; i < 4; i++) {
        pr[i] += __shfl_xor_sync(0xffffffffu, pr[i], 1);
        pr[i] += __shfl_xor_sync(0xffffffffu, pr[i], 2);
        pw[i] += __shfl_xor_sync(0xffffffffu, pw[i], 1);
        pw[i] += __shfl_xor_sync(0xffffffffu, pw[i], 2);
    }
    if (u == 0) {
        #pragma unroll
        for (int mt = 0; mt < 2; mt++)
            #pragma unroll
            for (int rh = 0; rh < 2; rh++) {
                int row = wm * 32 + mt * 16 + (lane >> 2) + rh * 8;
                atomicAdd(&outred[row], pr[mt * 2 + rh]);
                atomicAdd(&wared[row], pw[mt * 2 + rh]);
            }
    }
    __syncthreads();
    if (tid < 128) {
        int b = m0 + tid;
        atomicAdd(&out[b * Tn + t], outred[tid] * mask[b * Ln + t]);
        atomicAdd(&wa_g[(t + 1) & 1][b], wared[tid]);
    }
}

// ---------------- launch ----------------
extern "C" void kernel_launch(void* const* d_in, const int* in_sizes, int n_in,
                              void* d_out, int out_size)
{
    const float* input   = (const float*)d_in[0];
    const float* masks   = (const float*)d_in[1];
    const float* biasmat = (const float*)d_in[2];
    const float* conv1_w = (const float*)d_in[3];
    const float* conv1_b = (const float*)d_in[4];
    const float* conv_w  = (const float*)d_in[5];
    const float* conv_b  = (const float*)d_in[6];
    const float* w_ih    = (const float*)d_in[7];
    const float* w_hh    = (const float*)d_in[8];
    const float* b_ih    = (const float*)d_in[9];
    const float* b_hh    = (const float*)d_in[10];
    const float* fc1_w   = (const float*)d_in[11];
    const float* fc1_b   = (const float*)d_in[12];
    const float* conv2_w = (const float*)d_in[13];
    const float* conv2_b = (const float*)d_in[14];
    float* out = (float*)d_out;

    cudaFuncSetAttribute(step_mma, cudaFuncAttributeMaxDynamicSharedMemorySize, SMEM_DYN);

    conv_front<<<(Bn * Ln + 127) / 128, 128>>>(input, masks, conv1_w, conv1_b, conv_w, conv_b);
    build_B<<<(NG * KA + 255) / 256, 256>>>(w_hh, w_ih, b_ih, b_hh);
    init_state<<<(Bn * KA + 255) / 256, 256>>>(out, masks, conv2_b);

    dim3 ggrid(Bn / 128, NG / 128);   // (32, 16)
    for (int t = 0; t < Tn; t++) {
        attn_ctx<<<(Bn * 32 + 255) / 256, 256>>>(t, fc1_b, biasmat);
        step_mma<<<ggrid, 256, SMEM_DYN>>>(t, conv2_w, fc1_w, masks, out);
    }
}

// round 16
// speedup vs baseline: 1.0450x; 1.0450x over previous
#include <cuda_runtime.h>
#include <cuda_bf16.h>
#include <math.h>
#include <stdint.h>

#define Bn 4096
#define Ln 32
#define Cn 28
#define Hn 512
#define Tn 32
#define NG 2048          // 4*H
#define KA 1664          // 512 h_hi | 512 h_lo | 512 h_hi | 32 ctx_hi | 32 ctx_lo | 32 ctx_hi | 32 pad
#define NCHUNK 26        // KA / 64
#define ROWB 144         // 64 bf16 (128B) + 16B pad per smem row
#define BUFB (128 * ROWB)        // 18432 B per tile buffer
// dynamic smem: A0 A1 B0 B1  (2-stage double buffer — proven best)
#define AOFF 0
#define BOFF (2 * BUFB)
#define SMEM_DYN (4 * BUFB)      // 73728

// ---------------- device scratch ----------------
__device__ float x_g[Bn * Ln * Cn];
__device__ float ua_g[Bn * Ln];
__device__ float br_g[NG];
__device__ float c_g[Bn * Hn];
__device__ float wa_g[2][Bn];                              // ping-pong fc1 dot
__device__ __align__(16) __nv_bfloat16 A_bf[2][Bn * KA];   // ping-pong h/ctx splits
__device__ __align__(16) __nv_bfloat16 B_bf[NG * KA];

// ---------------- fast transcendentals (MUFU-based; rel err ~1e-6, budget 1e-3) ----
__device__ __forceinline__ float fsigmoid(float x) {
    return __frcp_rn(1.f + __expf(-x));
}
__device__ __forceinline__ float ftanh(float x) {
    float a = fabsf(x);
    float e = __expf(-2.f * a);                    // in (0,1]
    float r = 1.f - __fdividef(2.f * e, 1.f + e);  // tanh(|x|)
    return copysignf(r, x);
}

// ---------------- asm helpers ----------------
__device__ __forceinline__ uint32_t smem_u32(const void* p) {
    uint32_t a;
    asm("{ .reg .u64 t; cvta.to.shared.u64 t, %1; cvt.u32.u64 %0, t; }" : "=r"(a) : "l"(p));
    return a;
}
__device__ __forceinline__ void ldsm_x4(uint32_t a, uint32_t& r0, uint32_t& r1, uint32_t& r2, uint32_t& r3) {
    asm volatile("ldmatrix.sync.aligned.m8n8.x4.shared.b16 {%0,%1,%2,%3}, [%4];"
                 : "=r"(r0), "=r"(r1), "=r"(r2), "=r"(r3) : "r"(a));
}
__device__ __forceinline__ void mma_bf16(float* c, uint32_t a0, uint32_t a1, uint32_t a2, uint32_t a3,
                                         uint32_t b0, uint32_t b1) {
    asm volatile("mma.sync.aligned.m16n8k16.row.col.f32.bf16.bf16.f32 "
                 "{%0,%1,%2,%3},{%4,%5,%6,%7},{%8,%9},{%0,%1,%2,%3};"
                 : "+f"(c[0]), "+f"(c[1]), "+f"(c[2]), "+f"(c[3])
                 : "r"(a0), "r"(a1), "r"(a2), "r"(a3), "r"(b0), "r"(b1));
}
__device__ __forceinline__ void cpa16(uint32_t s, const void* g) {
    asm volatile("cp.async.cg.shared.global [%0], [%1], 16;" :: "r"(s), "l"(g));
}
__device__ __forceinline__ void cpa_commit() { asm volatile("cp.async.commit_group;" ::: "memory"); }
template <int N> __device__ __forceinline__ void cpa_wait() {
    asm volatile("cp.async.wait_group %0;" :: "n"(N) : "memory");
}

// ---------------- front-end conv ----------------
__global__ void conv_front(const float* __restrict__ in, const float* __restrict__ mask,
                           const float* __restrict__ w1, const float* __restrict__ b1,
                           const float* __restrict__ cw, const float* __restrict__ cb)
{
    __shared__ float ws[Cn * Cn * 3];
    __shared__ float cws[Cn];
    int tid = threadIdx.x;
    for (int i = tid; i < Cn * Cn * 3; i += blockDim.x) ws[i] = w1[i];
    if (tid < Cn) cws[tid] = cw[tid];
    __syncthreads();

    int idx = blockIdx.x * blockDim.x + tid;
    if (idx >= Bn * Ln) return;
    int b = idx / Ln, l = idx % Ln;

    float xin[3][Cn];
    #pragma unroll
    for (int k = 0; k < 3; k++) {
        int ll = l + k - 1;
        if (ll >= 0 && ll < Ln) {
            #pragma unroll
            for (int c = 0; c < Cn; c++) xin[k][c] = in[(b * Ln + ll) * Cn + c];
        } else {
            #pragma unroll
            for (int c = 0; c < Cn; c++) xin[k][c] = 0.f;
        }
    }
    float m = mask[idx];
    float ua = 0.f;
    for (int co = 0; co < Cn; co++) {
        float acc = b1[co];
        #pragma unroll
        for (int ci = 0; ci < Cn; ci++) {
            const float* wp = &ws[(co * Cn + ci) * 3];
            acc += xin[0][ci] * wp[0] + xin[1][ci] * wp[1] + xin[2][ci] * wp[2];
        }
        float ym = acc * m;
        float e  = ym > 0.f ? ym : (expf(ym) - 1.f);   // precise expf here: one-time kernel
        float xv = e + xin[1][co];
        x_g[idx * Cn + co] = xv;
        ua += xv * cws[co];
    }
    ua_g[idx] = (ua + cb[0]) * m;
}

// ---------------- build bf16-split B + bias (gate-interleaved n) ----------------
// n = 16*(j>>2) + 2*(j&3) + (g&1) + 8*(g>>1), g in {0:i,1:f,2:g,3:o}
__global__ void build_B(const float* __restrict__ whh, const float* __restrict__ wih,
                        const float* __restrict__ bih, const float* __restrict__ bhh)
{
    int idx = blockIdx.x * blockDim.x + threadIdx.x;
    if (idx < NG * KA) {
        int n = idx / KA, kl = idx % KA;
        int within = n & 15;
        int j = (n >> 4) * 4 + ((within & 7) >> 1);
        int g = (within & 1) + ((within >> 3) << 1);     // 0:i 1:f 2:g 3:o
        float v = 0.f; bool lo = false;
        if (kl < 512)        { v = whh[(g * Hn + j) * Hn + kl]; }
        else if (kl < 1024)  { v = whh[(g * Hn + j) * Hn + (kl - 512)]; }
        else if (kl < 1536)  { v = whh[(g * Hn + j) * Hn + (kl - 1024)]; lo = true; }
        else if (kl < 1632) {
            int c = (kl - 1536) & 31;
            int sec = (kl - 1536) >> 5;                  // 0: Wir_hi, 1: Wir_hi, 2: Wir_lo
            if (c < Cn) { v = wih[(g * Hn + j) * Cn + c]; lo = (sec == 2); }
        }                                                 // kl >= 1632: pad, v=0
        __nv_bfloat16 hi = __float2bfloat16(v);
        B_bf[idx] = lo ? __float2bfloat16(v - __bfloat162float(hi)) : hi;
    }
    if (idx < NG) {
        int within = idx & 15;
        int j = (idx >> 4) * 4 + ((within & 7) >> 1);
        int g = (within & 1) + ((within >> 3) << 1);
        br_g[idx] = bih[g * Hn + j] + bhh[g * Hn + j];
    }
}

// ---------------- init ----------------
__global__ void init_state(float* __restrict__ out, const float* __restrict__ mask,
                           const float* __restrict__ c2b)
{
    int idx = blockIdx.x * blockDim.x + threadIdx.x;
    if (idx < Bn * KA) ((uint32_t*)A_bf)[idx] = 0u;       // both ping-pong buffers
    if (idx < Bn * Hn) c_g[idx] = 0.f;
    if (idx < Bn) { wa_g[0][idx] = 0.f; wa_g[1][idx] = 0.f; }
    if (idx < Bn * Tn) out[idx] = c2b[0] * mask[idx];
}

// ---------------- per-step attention + context (writes ctx splits into A[t&1]) ----------------
__global__ void attn_ctx(int t, const float* __restrict__ fc1b, const float* __restrict__ bias)
{
    int gw = (blockIdx.x * blockDim.x + threadIdx.x) >> 5;
    int lane = threadIdx.x & 31;
    if (gw >= Bn) return;

    float wa = wa_g[t & 1][gw] + fc1b[0];
    if (lane == 0) wa_g[(t + 1) & 1][gw] = 0.f;   // zero accumulator for this step's epilogue

    float v = ua_g[gw * Ln + lane] + wa;
    float lr = v > 0.f ? v : 0.01f * v;
    float logit = lr + bias[gw * Ln + lane];
    float mx = logit;
    #pragma unroll
    for (int o = 16; o > 0; o >>= 1) mx = fmaxf(mx, __shfl_xor_sync(0xffffffffu, mx, o));
    float e = __expf(logit - mx);
    float se = e;
    #pragma unroll
    for (int o = 16; o > 0; o >>= 1) se += __shfl_xor_sync(0xffffffffu, se, o);
    float attn = __fdividef(e, se);

    float ctx = 0.f;
    const float* xb = x_g + (size_t)gw * Ln * Cn;
    #pragma unroll
    for (int l = 0; l < Ln; l++) {
        float al = __shfl_sync(0xffffffffu, attn, l);
        if (lane < Cn) ctx = fmaf(al, xb[l * Cn + lane], ctx);
    }
    if (lane < Cn) {
        __nv_bfloat16 hi = __float2bfloat16(ctx);
        __nv_bfloat16 lo = __float2bfloat16(ctx - __bfloat162float(hi));
        __nv_bfloat16* ab = A_bf[t & 1] + (size_t)gw * KA + 1536;
        ab[lane] = hi; ab[32 + lane] = lo; ab[64 + lane] = hi;
    }
}

// ---------------- per-step HMMA GEMM (128x128 tile, K-chunk 64, 2-stage) + LSTM epilogue ----------------
__global__ void __launch_bounds__(256, 2) step_mma(int t, const float* __restrict__ c2w,
                                                   const float* __restrict__ fc1w,
                                                   const float* __restrict__ mask,
                                                   float* __restrict__ out)
{
    extern __shared__ __align__(16) char dsm[];
    __shared__ float outred[128];
    __shared__ float wared[128];

    int tid = threadIdx.x;
    int lane = tid & 31, wid = tid >> 5;
    int wm = wid & 3, wn = wid >> 2;
    int m0 = blockIdx.x * 128;
    int n0 = blockIdx.y * 128;

    uint32_t sbase = smem_u32(dsm);

    const __nv_bfloat16* Ag = A_bf[t & 1] + (size_t)m0 * KA;        // read h_t / ctx_t
    __nv_bfloat16* Anext = A_bf[(t + 1) & 1];                       // write h_{t+1}
    const __nv_bfloat16* Bg = B_bf + (size_t)n0 * KA;

    // loader: 32 rows/pass x 8x16B parts; 4 passes per tensor per chunk
    int lm = tid >> 3;            // 0..31
    int lp = tid & 7;             // 16B part (128B per row)

    #define LOADAB(cc, buf) do {                                                         \
        int _k0 = (cc) * 64;                                                             \
        _Pragma("unroll")                                                                \
        for (int s = 0; s < 4; s++) {                                                    \
            int m = s * 32 + lm;                                                         \
            cpa16(sbase + AOFF + (buf) * BUFB + m * ROWB + lp * 16,                      \
                  Ag + (size_t)m * KA + _k0 + lp * 8);                                   \
            cpa16(sbase + BOFF + (buf) * BUFB + m * ROWB + lp * 16,                      \
                  Bg + (size_t)m * KA + _k0 + lp * 8);                                   \
        }                                                                                \
    } while (0)

    LOADAB(0, 0); cpa_commit();
    LOADAB(1, 1); cpa_commit();

    float acc[2][8][4];
    #pragma unroll
    for (int i = 0; i < 2; i++)
        #pragma unroll
        for (int j = 0; j < 8; j++)
            #pragma unroll
            for (int k = 0; k < 4; k++) acc[i][j][k] = 0.f;

    int a_row_lo = (lane & 7) + ((lane >> 3) & 1) * 8;
    int a_kb     = (lane >> 4) * 16;
    int b_row_lo = (lane & 7) + ((lane >> 4) & 1) * 8;
    int b_kb     = ((lane >> 3) & 1) * 16;

    for (int c = 0; c < NCHUNK; c++) {
        int buf = c & 1;
        if (c < NCHUNK - 1) cpa_wait<1>();
        else                cpa_wait<0>();
        __syncthreads();

        uint32_t ab = sbase + AOFF + buf * BUFB;
        uint32_t bb = sbase + BOFF + buf * BUFB;
        #pragma unroll
        for (int kk = 0; kk < 4; kk++) {
            int kb = kk * 32;    // 16 bf16 = 32B per k-step
            uint32_t af[2][4];
            #pragma unroll
            for (int mt = 0; mt < 2; mt++)
                ldsm_x4(ab + (wm * 32 + mt * 16 + a_row_lo) * ROWB + kb + a_kb,
                        af[mt][0], af[mt][1], af[mt][2], af[mt][3]);
            #pragma unroll
            for (int p = 0; p < 4; p++) {
                uint32_t b0, b1, b2, b3;
                ldsm_x4(bb + (wn * 64 + p * 16 + b_row_lo) * ROWB + kb + b_kb, b0, b1, b2, b3);
                #pragma unroll
                for (int mt = 0; mt < 2; mt++) {
                    mma_bf16(acc[mt][p * 2 + 0], af[mt][0], af[mt][1], af[mt][2], af[mt][3], b0, b1);
                    mma_bf16(acc[mt][p * 2 + 1], af[mt][0], af[mt][1], af[mt][2], af[mt][3], b2, b3);
                }
            }
        }
        __syncthreads();
        if (c + 2 < NCHUNK) { LOADAB(c + 2, buf); cpa_commit(); }
    }

    // ---- epilogue: LSTM cell + out dot + fc1 dot + bf16-split h into A[(t+1)&1] ----
    if (tid < 128) { outred[tid] = 0.f; wared[tid] = 0.f; }
    __syncthreads();

    float pr[4] = {0.f, 0.f, 0.f, 0.f};
    float pw[4] = {0.f, 0.f, 0.f, 0.f};
    int u = lane & 3;

    #pragma unroll
    for (int p = 0; p < 4; p++) {
        int nb16 = n0 + wn * 64 + p * 16;
        int j = (nb16 >> 4) * 4 + u;
        float bi  = br_g[nb16 + u * 2 + 0];
        float bfv = br_g[nb16 + u * 2 + 1];
        float bg  = br_g[nb16 + 8 + u * 2 + 0];
        float bo  = br_g[nb16 + 8 + u * 2 + 1];
        float wc2 = c2w[j], wf1 = fc1w[j];
        #pragma unroll
        for (int mt = 0; mt < 2; mt++) {
            #pragma unroll
            for (int rh = 0; rh < 2; rh++) {
                int row = wm * 32 + mt * 16 + (lane >> 2) + rh * 8;
                int b = m0 + row;
                float ig = acc[mt][p * 2 + 0][rh * 2 + 0] + bi;
                float fg = acc[mt][p * 2 + 0][rh * 2 + 1] + bfv;
                float gg = acc[mt][p * 2 + 1][rh * 2 + 0] + bg;
                float og = acc[mt][p * 2 + 1][rh * 2 + 1] + bo;
                float si = fsigmoid(ig);
                float sf = fsigmoid(fg);
                float so = fsigmoid(og);
                float cnew = sf * c_g[b * Hn + j] + si * ftanh(gg);
                float hn = so * ftanh(cnew);
                c_g[b * Hn + j] = cnew;
                __nv_bfloat16 hi = __float2bfloat16(hn);
                __nv_bfloat16 lo = __float2bfloat16(hn - __bfloat162float(hi));
                __nv_bfloat16* arow = Anext + (size_t)b * KA;
                arow[j] = hi; arow[512 + j] = lo; arow[1024 + j] = hi;
                pr[mt * 2 + rh] = fmaf(hn, wc2, pr[mt * 2 + rh]);
                pw[mt * 2 + rh] = fmaf(hn, wf1, pw[mt * 2 + rh]);
            }
        }
    }
    #pragma unroll
    for (int i = 0; i < 4; i++) {
        pr[i] += __shfl_xor_sync(0xffffffffu, pr[i], 1);
        pr[i] += __shfl_xor_sync(0xffffffffu, pr[i], 2);
        pw[i] += __shfl_xor_sync(0xffffffffu, pw[i], 1);
        pw[i] += __shfl_xor_sync(0xffffffffu, pw[i], 2);
    }
    if (u == 0) {
        #pragma unroll
        for (int mt = 0; mt < 2; mt++)
            #pragma unroll
            for (int rh = 0; rh < 2; rh++) {
                int row = wm * 32 + mt * 16 + (lane >> 2) + rh * 8;
                atomicAdd(&outred[row], pr[mt * 2 + rh]);
                atomicAdd(&wared[row], pw[mt * 2 + rh]);
            }
    }
    __syncthreads();
    if (tid < 128) {
        int b = m0 + tid;
        atomicAdd(&out[b * Tn + t], outred[tid] * mask[b * Ln + t]);
        atomicAdd(&wa_g[(t + 1) & 1][b], wared[tid]);
    }
}

// ---------------- launch ----------------
extern "C" void kernel_launch(void* const* d_in, const int* in_sizes, int n_in,
                              void* d_out, int out_size)
{
    const float* input   = (const float*)d_in[0];
    const float* masks   = (const float*)d_in[1];
    const float* biasmat = (const float*)d_in[2];
    const float* conv1_w = (const float*)d_in[3];
    const float* conv1_b = (const float*)d_in[4];
    const float* conv_w  = (const float*)d_in[5];
    const float* conv_b  = (const float*)d_in[6];
    const float* w_ih    = (const float*)d_in[7];
    const float* w_hh    = (const float*)d_in[8];
    const float* b_ih    = (const float*)d_in[9];
    const float* b_hh    = (const float*)d_in[10];
    const float* fc1_w   = (const float*)d_in[11];
    const float* fc1_b   = (const float*)d_in[12];
    const float* conv2_w = (const float*)d_in[13];
    const float* conv2_b = (const float*)d_in[14];
    float* out = (float*)d_out;

    cudaFuncSetAttribute(step_mma, cudaFuncAttributeMaxDynamicSharedMemorySize, SMEM_DYN);

    conv_front<<<(Bn * Ln + 127) / 128, 128>>>(input, masks, conv1_w, conv1_b, conv_w, conv_b);
    build_B<<<(NG * KA + 255) / 256, 256>>>(w_hh, w_ih, b_ih, b_hh);
    init_state<<<(Bn * KA + 255) / 256, 256>>>(out, masks, conv2_b);

    dim3 ggrid(Bn / 128, NG / 128);   // (32, 16)
    for (int t = 0; t < Tn; t++) {
        attn_ctx<<<(Bn * 32 + 255) / 256, 256>>>(t, fc1_b, biasmat);
        step_mma<<<ggrid, 256, SMEM_DYN>>>(t, conv2_w, fc1_w, masks, out);
    }
}